// round 7
// baseline (speedup 1.0000x reference)
#include <cuda_runtime.h>
#include <cstdint>

#define NN 100000
#define NE 1600000
#define FD 128
#define NG 64
#define NC 32

#define NBLK ((NN + 255) / 256)   // 391 scan blocks

// ---------------- scratch (static device globals; allocation-free) ----------
__device__ int    g_deg[NN];
__device__ int    g_offs[NN + 1];
__device__ int    g_cursor[NN];
__device__ float2 g_edge[NE];          // (.x = src idx bitcast, .y = weight)
__device__ float  g_dinv[NN];
__device__ int    g_bsum[NBLK];
__device__ float  g_bufA[(size_t)NN * FD];
__device__ float  g_bufB[(size_t)NN * FD];
__device__ float  g_pooled[NG * FD];

// ---------------- helpers -----------------------------------------------------
__device__ __forceinline__ uint32_t f2tf32(float x) {
    uint32_t r; asm("cvt.rna.tf32.f32 %0, %1;" : "=r"(r) : "f"(x)); return r;
}

__device__ __forceinline__ void mma_tf32(float* d, const uint32_t* a, uint32_t b0, uint32_t b1) {
    asm volatile("mma.sync.aligned.m16n8k8.row.col.f32.tf32.tf32.f32 "
                 "{%0,%1,%2,%3}, {%4,%5,%6,%7}, {%8,%9}, {%0,%1,%2,%3};"
                 : "+f"(d[0]), "+f"(d[1]), "+f"(d[2]), "+f"(d[3])
                 : "r"(a[0]), "r"(a[1]), "r"(a[2]), "r"(a[3]), "r"(b0), "r"(b1));
}

__device__ __forceinline__ void cp_async16(uint32_t saddr, const void* gptr, int src_bytes) {
    asm volatile("cp.async.ca.shared.global [%0], [%1], 16, %2;"
                 :: "r"(saddr), "l"(gptr), "r"(src_bytes));
}

// ---------------- init: zero deg ------------------------------------------------
__global__ void k_init() {
    int i = blockIdx.x * blockDim.x + threadIdx.x;
    if (i < NN) g_deg[i] = 0;
}

__global__ void k_deg(const int* __restrict__ dst, int ne) {
    int i = blockIdx.x * blockDim.x + threadIdx.x;
    if (i < ne) atomicAdd(&g_deg[dst[i]], 1);
}

// ---------------- 3-phase scan ------------------------------------------------
__global__ void k_blocksum() {
    __shared__ int s[256];
    int i = blockIdx.x * 256 + threadIdx.x;
    s[threadIdx.x] = (i < NN) ? g_deg[i] : 0;
    __syncthreads();
    for (int d = 128; d > 0; d >>= 1) {
        if (threadIdx.x < d) s[threadIdx.x] += s[threadIdx.x + d];
        __syncthreads();
    }
    if (threadIdx.x == 0) g_bsum[blockIdx.x] = s[0];
}

__global__ void k_scanpartials() {
    __shared__ int s[512];
    int tid = threadIdx.x;
    s[tid] = (tid < NBLK) ? g_bsum[tid] : 0;
    __syncthreads();
    for (int d = 1; d < 512; d <<= 1) {
        int v = (tid >= d) ? s[tid - d] : 0;
        __syncthreads();
        s[tid] += v;
        __syncthreads();
    }
    if (tid < NBLK) g_bsum[tid] = (tid ? s[tid - 1] : 0);   // exclusive block sums
    if (tid == 0) g_offs[NN] = s[511];
}

__global__ void k_offsets() {
    __shared__ int warp_sums[8];
    int tid = threadIdx.x;
    int i = blockIdx.x * 256 + tid;
    int v = (i < NN) ? g_deg[i] : 0;
    int x = v;
    #pragma unroll
    for (int d = 1; d < 32; d <<= 1) {
        int y = __shfl_up_sync(0xffffffffu, x, d);
        if ((tid & 31) >= d) x += y;
    }
    if ((tid & 31) == 31) warp_sums[tid >> 5] = x;
    __syncthreads();
    if (tid < 8) {
        int y = warp_sums[tid];
        #pragma unroll
        for (int d = 1; d < 8; d <<= 1) {
            int z = __shfl_up_sync(0xffu, y, d);
            if (tid >= d) y += z;
        }
        warp_sums[tid] = y;
    }
    __syncthreads();
    int incl = x + ((tid >= 32) ? warp_sums[(tid >> 5) - 1] : 0);
    int excl = incl - v + g_bsum[blockIdx.x];
    if (i < NN) {
        g_offs[i] = excl;
        g_cursor[i] = excl;
        g_dinv[i] = rsqrtf((float)v + 1.0f);
    }
}

// ---------------- CSR scatter with fused edge weight ---------------------------
__global__ void k_scatter(const int* __restrict__ src,
                          const int* __restrict__ dst, int ne) {
    int i = blockIdx.x * blockDim.x + threadIdx.x;
    if (i < ne) {
        int d = dst[i];
        int sN = src[i];
        float w = g_dinv[d] * g_dinv[sN];
        int pos = atomicAdd(&g_cursor[d], 1);
        g_edge[pos] = make_float2(__int_as_float(sN), w);
    }
}

// ---------------- tf32 tensor-core GEMM: C[n,128] = A[n,128] @ W[128,128] ------
// Single-term tf32. 3-stage cp.async ring over k=32 chunks of BOTH A and W.
#define AS_STRIDE 36
#define WS_STRIDE 132
#define A_CHUNK_FLOATS (128 * AS_STRIDE)     // 4608
#define W_CHUNK_FLOATS (32 * WS_STRIDE)      // 4224
#define STAGE_FLOATS (A_CHUNK_FLOATS + W_CHUNK_FLOATS)
#define NSTAGE 3
#define GEMM_SMEM (NSTAGE * STAGE_FLOATS * 4)   // 105,984 B

__global__ __launch_bounds__(256, 2) void k_gemm_tf32(const float* __restrict__ A,
                                                      const float* __restrict__ W,
                                                      float* __restrict__ C, int nrows) {
    extern __shared__ float smem[];

    int tid = threadIdx.x;
    int row0 = blockIdx.x * 128;
    uint32_t sm_base = (uint32_t)__cvta_generic_to_shared(smem);

    // async chunk loader: chunk c covers k = 32c..32c+31; stage s = c % NSTAGE
    auto load_chunk = [&](int c) {
        int st = c % NSTAGE;
        uint32_t a_base = sm_base + (uint32_t)(st * STAGE_FLOATS) * 4;
        uint32_t w_base = a_base + (uint32_t)A_CHUNK_FLOATS * 4;
        #pragma unroll
        for (int i = 0; i < 4; i++) {
            int idx = tid + i * 256;          // 0..1023
            // A: 128 rows x 8 quads
            int r = idx >> 3, q = idx & 7;
            const float* ga = A + (size_t)(row0 + r) * FD + c * 32 + q * 4;
            cp_async16(a_base + (uint32_t)(r * AS_STRIDE + q * 4) * 4, ga,
                       (row0 + r < nrows) ? 16 : 0);
            // W: 32 rows x 32 quads
            int wr_ = idx >> 5, wq = idx & 31;
            const float* gw = W + (size_t)(c * 32 + wr_) * FD + wq * 4;
            cp_async16(w_base + (uint32_t)(wr_ * WS_STRIDE + wq * 4) * 4, gw, 16);
        }
        asm volatile("cp.async.commit_group;" ::: "memory");
    };

    int lane = tid & 31;
    int wid  = tid >> 5;
    int wr = wid & 3;        // rows 32*wr..
    int wc = wid >> 2;       // cols 64*wc..
    int qrow = lane >> 2;
    int qcol = lane & 3;

    float acc[2][8][4];
    #pragma unroll
    for (int s = 0; s < 2; s++)
        #pragma unroll
        for (int t = 0; t < 8; t++)
            #pragma unroll
            for (int q = 0; q < 4; q++) acc[s][t][q] = 0.f;

    load_chunk(0);
    load_chunk(1);

    #pragma unroll
    for (int c = 0; c < 4; c++) {
        if (c + 2 < 4) load_chunk(c + 2);
        // wait until chunk c complete: allow (issued - (c+1)) groups in flight
        if (c == 0)      asm volatile("cp.async.wait_group 2;" ::: "memory");
        else if (c == 1) asm volatile("cp.async.wait_group 2;" ::: "memory");
        else if (c == 2) asm volatile("cp.async.wait_group 1;" ::: "memory");
        else             asm volatile("cp.async.wait_group 0;" ::: "memory");
        __syncthreads();

        const float* Ab = smem + (c % NSTAGE) * STAGE_FLOATS;
        const float* Wb = Ab + A_CHUNK_FLOATS;

        #pragma unroll
        for (int kk2 = 0; kk2 < 4; kk2++) {
            int k0 = kk2 * 8;                 // within chunk
            uint32_t af[2][4];
            #pragma unroll
            for (int s = 0; s < 2; s++) {
                int rb = 32 * wr + 16 * s + qrow;
                af[s][0] = f2tf32(Ab[(rb)     * AS_STRIDE + k0 + qcol]);
                af[s][1] = f2tf32(Ab[(rb + 8) * AS_STRIDE + k0 + qcol]);
                af[s][2] = f2tf32(Ab[(rb)     * AS_STRIDE + k0 + qcol + 4]);
                af[s][3] = f2tf32(Ab[(rb + 8) * AS_STRIDE + k0 + qcol + 4]);
            }
            #pragma unroll
            for (int t = 0; t < 8; t++) {
                int n = 64 * wc + 8 * t + qrow;
                uint32_t b0 = f2tf32(Wb[(k0 + qcol)     * WS_STRIDE + n]);
                uint32_t b1 = f2tf32(Wb[(k0 + qcol + 4) * WS_STRIDE + n]);
                mma_tf32(acc[0][t], af[0], b0, b1);
                mma_tf32(acc[1][t], af[1], b0, b1);
            }
        }
        __syncthreads();   // stage buffer reuse guard
    }

    #pragma unroll
    for (int s = 0; s < 2; s++) {
        int rbase = row0 + 32 * wr + 16 * s + qrow;
        #pragma unroll
        for (int t = 0; t < 8; t++) {
            int col = 64 * wc + 8 * t + 2 * qcol;
            if (rbase < nrows)
                *(float2*)(C + (size_t)rbase * FD + col) = make_float2(acc[s][t][0], acc[s][t][1]);
            if (rbase + 8 < nrows)
                *(float2*)(C + (size_t)(rbase + 8) * FD + col) = make_float2(acc[s][t][2], acc[s][t][3]);
        }
    }
}

// ---------------- GCN aggregation: warp/node, streamed (src,w) edges -----------
__global__ void k_agg(const float* __restrict__ h, const float* __restrict__ bias,
                      float* __restrict__ out) {
    int gw = (blockIdx.x * blockDim.x + threadIdx.x) >> 5;
    if (gw >= NN) return;
    int lane = threadIdx.x & 31;
    int s = g_offs[gw], e = g_offs[gw + 1];

    float4 acc0 = make_float4(0.f, 0.f, 0.f, 0.f);
    float4 acc1 = make_float4(0.f, 0.f, 0.f, 0.f);

    int j = s;
    for (; j + 8 <= e; j += 8) {
        float2 ed[8];
        #pragma unroll
        for (int u = 0; u < 8; u++) ed[u] = g_edge[j + u];
        float4 v[8];
        #pragma unroll
        for (int u = 0; u < 8; u++)
            v[u] = ((const float4*)(h + (size_t)__float_as_int(ed[u].x) * FD))[lane];
        #pragma unroll
        for (int u = 0; u < 8; u += 2) {
            acc0.x = fmaf(ed[u].y, v[u].x, acc0.x); acc0.y = fmaf(ed[u].y, v[u].y, acc0.y);
            acc0.z = fmaf(ed[u].y, v[u].z, acc0.z); acc0.w = fmaf(ed[u].y, v[u].w, acc0.w);
            acc1.x = fmaf(ed[u+1].y, v[u+1].x, acc1.x); acc1.y = fmaf(ed[u+1].y, v[u+1].y, acc1.y);
            acc1.z = fmaf(ed[u+1].y, v[u+1].z, acc1.z); acc1.w = fmaf(ed[u+1].y, v[u+1].w, acc1.w);
        }
    }
    for (; j < e; j++) {
        float2 ej = g_edge[j];
        float4 v = ((const float4*)(h + (size_t)__float_as_int(ej.x) * FD))[lane];
        acc0.x = fmaf(ej.y, v.x, acc0.x); acc0.y = fmaf(ej.y, v.y, acc0.y);
        acc0.z = fmaf(ej.y, v.z, acc0.z); acc0.w = fmaf(ej.y, v.w, acc0.w);
    }
    {   // self loop
        float di = g_dinv[gw];
        float w = di * di;
        float4 v = ((const float4*)(h + (size_t)gw * FD))[lane];
        acc0.x = fmaf(w, v.x, acc0.x); acc0.y = fmaf(w, v.y, acc0.y);
        acc0.z = fmaf(w, v.z, acc0.z); acc0.w = fmaf(w, v.w, acc0.w);
    }
    float4 b4 = ((const float4*)bias)[lane];
    float4 r;
    r.x = fmaxf(acc0.x + acc1.x + b4.x, 0.f);
    r.y = fmaxf(acc0.y + acc1.y + b4.y, 0.f);
    r.z = fmaxf(acc0.z + acc1.z + b4.z, 0.f);
    r.w = fmaxf(acc0.w + acc1.w + b4.w, 0.f);
    ((float4*)(out + (size_t)gw * FD))[lane] = r;
}

// ---------------- per-graph mean pool (binary-search boundaries) ---------------
__global__ void k_pool(const float* __restrict__ h, const int* __restrict__ bat) {
    int g = blockIdx.x;
    __shared__ int se[2];
    if (threadIdx.x < 2) {
        int target = g + threadIdx.x;
        int lo = 0, hi = NN;
        while (lo < hi) { int m = (lo + hi) >> 1; if (bat[m] < target) lo = m + 1; else hi = m; }
        se[threadIdx.x] = lo;
    }
    __syncthreads();
    int s = se[0], e = se[1];
    int c = blockIdx.y * 32 + threadIdx.x;   // gridDim.y = 4
    float acc0 = 0.f, acc1 = 0.f, acc2 = 0.f, acc3 = 0.f;
    int i = s;
    for (; i + 4 <= e; i += 4) {
        acc0 += h[(size_t)(i + 0) * FD + c];
        acc1 += h[(size_t)(i + 1) * FD + c];
        acc2 += h[(size_t)(i + 2) * FD + c];
        acc3 += h[(size_t)(i + 3) * FD + c];
    }
    for (; i < e; i++) acc0 += h[(size_t)i * FD + c];
    float cnt = (float)((e - s) > 1 ? (e - s) : 1);
    g_pooled[g * FD + c] = (acc0 + acc1 + acc2 + acc3) / cnt;
}

// ---------------- final FC -------------------------------------------------------
__global__ void k_fc(const float* __restrict__ fcW, const float* __restrict__ fcb,
                     float* __restrict__ out) {
    int g = blockIdx.x;
    int c = threadIdx.x;
    float acc = fcb[c];
    #pragma unroll 4
    for (int k = 0; k < FD; k++)
        acc = fmaf(g_pooled[g * FD + k], fcW[k * NC + c], acc);
    out[g * NC + c] = acc;
}

// ---------------- launch ----------------------------------------------------------
extern "C" void kernel_launch(void* const* d_in, const int* in_sizes, int n_in,
                              void* d_out, int out_size) {
    const float* x    = (const float*)d_in[0];
    const int*   ei   = (const int*)d_in[1];
    const int*   bat  = (const int*)d_in[2];
    const float* W1   = (const float*)d_in[3];
    const float* b1   = (const float*)d_in[4];
    const float* W2   = (const float*)d_in[5];
    const float* b2   = (const float*)d_in[6];
    const float* fcW  = (const float*)d_in[7];
    const float* fcb  = (const float*)d_in[8];
    float* out = (float*)d_out;

    int ne = in_sizes[1] / 2;
    const int* src = ei;
    const int* dst = ei + ne;

    float *bufA, *bufB;
    cudaGetSymbolAddress((void**)&bufA, g_bufA);
    cudaGetSymbolAddress((void**)&bufB, g_bufB);

    cudaFuncSetAttribute(k_gemm_tf32, cudaFuncAttributeMaxDynamicSharedMemorySize, GEMM_SMEM);

    int tb = 256;
    int gbN   = (NN + tb - 1) / tb;
    int gbE   = (ne + tb - 1) / tb;
    int gbAgg = (NN * 32 + tb - 1) / tb;
    int gbGemm = (NN + 127) / 128;

    // ordered so launch index 3 (profiled slot) is the layer-1 GEMM
    k_init<<<gbN, tb>>>();                                          // 0
    k_deg<<<gbE, tb>>>(dst, ne);                                    // 1
    k_blocksum<<<NBLK, tb>>>();                                     // 2
    k_gemm_tf32<<<gbGemm, tb, GEMM_SMEM>>>(x, W1, bufA, NN);        // 3 <- profiled
    k_scanpartials<<<1, 512>>>();                                   // 4
    k_offsets<<<NBLK, tb>>>();                                      // 5
    k_scatter<<<gbE, tb>>>(src, dst, ne);                           // 6
    k_agg<<<gbAgg, tb>>>(bufA, b1, bufB);                           // 7
    k_gemm_tf32<<<gbGemm, tb, GEMM_SMEM>>>(bufB, W2, bufA, NN);     // 8
    k_agg<<<gbAgg, tb>>>(bufA, b2, bufB);                           // 9
    k_pool<<<dim3(NG, 4), 32>>>(bufB, bat);                         // 10
    k_fc<<<NG, NC>>>(fcW, fcb, out);                                // 11
}

// round 8
// speedup vs baseline: 1.0071x; 1.0071x over previous
#include <cuda_runtime.h>
#include <cstdint>

#define NN 100000
#define NE 1600000
#define FD 128
#define NG 64
#define NC 32

#define NBLK ((NN + 255) / 256)   // 391 scan blocks

// ---------------- scratch (static device globals; allocation-free) ----------
__device__ int    g_deg[NN];
__device__ int    g_offs[NN + 1];
__device__ int    g_cursor[NN];
__device__ float2 g_edge[NE];          // (.x = src idx bitcast, .y = weight)
__device__ float  g_dinv[NN];
__device__ int    g_bsum[NBLK];
__device__ float  g_bufA[(size_t)NN * FD];
__device__ float  g_bufB[(size_t)NN * FD];
__device__ float  g_pooled[NG * FD];

// ---------------- helpers -----------------------------------------------------
__device__ __forceinline__ uint32_t f2tf32(float x) {
    uint32_t r; asm("cvt.rna.tf32.f32 %0, %1;" : "=r"(r) : "f"(x)); return r;
}

__device__ __forceinline__ void mma_tf32(float* d, const uint32_t* a, uint32_t b0, uint32_t b1) {
    asm volatile("mma.sync.aligned.m16n8k8.row.col.f32.tf32.tf32.f32 "
                 "{%0,%1,%2,%3}, {%4,%5,%6,%7}, {%8,%9}, {%0,%1,%2,%3};"
                 : "+f"(d[0]), "+f"(d[1]), "+f"(d[2]), "+f"(d[3])
                 : "r"(a[0]), "r"(a[1]), "r"(a[2]), "r"(a[3]), "r"(b0), "r"(b1));
}

__device__ __forceinline__ void cp_async16(uint32_t saddr, const void* gptr, int src_bytes) {
    asm volatile("cp.async.ca.shared.global [%0], [%1], 16, %2;"
                 :: "r"(saddr), "l"(gptr), "r"(src_bytes));
}

// ---------------- init: zero deg ------------------------------------------------
__global__ void k_init() {
    int i = blockIdx.x * blockDim.x + threadIdx.x;
    if (i < NN) g_deg[i] = 0;
}

__global__ void k_deg(const int* __restrict__ dst, int ne) {
    int i = blockIdx.x * blockDim.x + threadIdx.x;
    if (i < ne) atomicAdd(&g_deg[dst[i]], 1);
}

// ---------------- 3-phase scan ------------------------------------------------
__global__ void k_blocksum() {
    __shared__ int s[256];
    int i = blockIdx.x * 256 + threadIdx.x;
    s[threadIdx.x] = (i < NN) ? g_deg[i] : 0;
    __syncthreads();
    for (int d = 128; d > 0; d >>= 1) {
        if (threadIdx.x < d) s[threadIdx.x] += s[threadIdx.x + d];
        __syncthreads();
    }
    if (threadIdx.x == 0) g_bsum[blockIdx.x] = s[0];
}

__global__ void k_scanpartials() {
    __shared__ int s[512];
    int tid = threadIdx.x;
    s[tid] = (tid < NBLK) ? g_bsum[tid] : 0;
    __syncthreads();
    for (int d = 1; d < 512; d <<= 1) {
        int v = (tid >= d) ? s[tid - d] : 0;
        __syncthreads();
        s[tid] += v;
        __syncthreads();
    }
    if (tid < NBLK) g_bsum[tid] = (tid ? s[tid - 1] : 0);   // exclusive block sums
    if (tid == 0) g_offs[NN] = s[511];
}

__global__ void k_offsets() {
    __shared__ int warp_sums[8];
    int tid = threadIdx.x;
    int i = blockIdx.x * 256 + tid;
    int v = (i < NN) ? g_deg[i] : 0;
    int x = v;
    #pragma unroll
    for (int d = 1; d < 32; d <<= 1) {
        int y = __shfl_up_sync(0xffffffffu, x, d);
        if ((tid & 31) >= d) x += y;
    }
    if ((tid & 31) == 31) warp_sums[tid >> 5] = x;
    __syncthreads();
    if (tid < 8) {
        int y = warp_sums[tid];
        #pragma unroll
        for (int d = 1; d < 8; d <<= 1) {
            int z = __shfl_up_sync(0xffu, y, d);
            if (tid >= d) y += z;
        }
        warp_sums[tid] = y;
    }
    __syncthreads();
    int incl = x + ((tid >= 32) ? warp_sums[(tid >> 5) - 1] : 0);
    int excl = incl - v + g_bsum[blockIdx.x];
    if (i < NN) {
        g_offs[i] = excl;
        g_cursor[i] = excl;
        g_dinv[i] = rsqrtf((float)v + 1.0f);
    }
}

// ---------------- CSR scatter with fused edge weight ---------------------------
__global__ void k_scatter(const int* __restrict__ src,
                          const int* __restrict__ dst, int ne) {
    int i = blockIdx.x * blockDim.x + threadIdx.x;
    if (i < ne) {
        int d = dst[i];
        int sN = src[i];
        float w = g_dinv[d] * g_dinv[sN];
        int pos = atomicAdd(&g_cursor[d], 1);
        __stcs(&g_edge[pos], make_float2(__int_as_float(sN), w));
    }
}

// ---------------- tf32 tensor-core GEMM: C[n,128] = A[n,128] @ W[128,128] ------
// Single-term tf32. W resident in smem (converted once); A double-buffered k=32
// chunks via cp.async. Streaming stores on C (keep L2 for the agg gathers).
#define WS_STRIDE 136
#define AS_STRIDE 36
#define A_CHUNK_FLOATS (128 * AS_STRIDE)     // 4608 per buffer
#define GEMM_SMEM ((128 * WS_STRIDE + 2 * A_CHUNK_FLOATS) * 4)   // 106,496 B

__global__ __launch_bounds__(256, 2) void k_gemm_tf32(const float* __restrict__ A,
                                                      const float* __restrict__ W,
                                                      float* __restrict__ C, int nrows) {
    extern __shared__ float smem[];
    float* Ws = smem;                         // [128][136] tf32-converted
    float* As = smem + 128 * WS_STRIDE;       // [2][128][36] fp32

    int tid = threadIdx.x;
    int row0 = blockIdx.x * 128;
    uint32_t as_base = (uint32_t)__cvta_generic_to_shared(As);

    // load full W tile, converting to tf32 once
    for (int i = tid; i < 128 * 32; i += 256) {
        int r = i >> 5, c = i & 31;
        float4 v = ((const float4*)(W + (size_t)r * FD))[c];
        float* d = Ws + r * WS_STRIDE + c * 4;
        d[0] = __uint_as_float(f2tf32(v.x));
        d[1] = __uint_as_float(f2tf32(v.y));
        d[2] = __uint_as_float(f2tf32(v.z));
        d[3] = __uint_as_float(f2tf32(v.w));
    }

    // async A chunk loader: chunk c covers k = 32c..32c+31
    auto load_chunk = [&](int c, int buf) {
        #pragma unroll
        for (int i = 0; i < 4; i++) {
            int idx = tid + i * 256;          // 0..1023
            int r = idx >> 3;                 // 0..127
            int q = idx & 7;                  // 0..7 (float4 quads)
            const float* g = A + (size_t)(row0 + r) * FD + c * 32 + q * 4;
            uint32_t s = as_base + (uint32_t)(buf * A_CHUNK_FLOATS + r * AS_STRIDE + q * 4) * 4;
            cp_async16(s, g, (row0 + r < nrows) ? 16 : 0);
        }
    };

    int lane = tid & 31;
    int wid  = tid >> 5;
    int wr = wid & 3;        // rows 32*wr..
    int wc = wid >> 2;       // cols 64*wc..
    int qrow = lane >> 2;
    int qcol = lane & 3;

    float acc[2][8][4];
    #pragma unroll
    for (int s = 0; s < 2; s++)
        #pragma unroll
        for (int t = 0; t < 8; t++)
            #pragma unroll
            for (int q = 0; q < 4; q++) acc[s][t][q] = 0.f;

    load_chunk(0, 0);
    asm volatile("cp.async.commit_group;" ::: "memory");

    #pragma unroll
    for (int c = 0; c < 4; c++) {
        int buf = c & 1;
        if (c < 3) {
            load_chunk(c + 1, buf ^ 1);
            asm volatile("cp.async.commit_group;" ::: "memory");
            asm volatile("cp.async.wait_group 1;" ::: "memory");
        } else {
            asm volatile("cp.async.wait_group 0;" ::: "memory");
        }
        __syncthreads();

        const float* Ab = As + buf * A_CHUNK_FLOATS;
        #pragma unroll
        for (int kk2 = 0; kk2 < 4; kk2++) {
            int k0 = kk2 * 8;                 // within chunk
            int K0 = c * 32 + k0;             // within full K (for W)
            uint32_t af[2][4];
            #pragma unroll
            for (int s = 0; s < 2; s++) {
                int rb = 32 * wr + 16 * s + qrow;
                af[s][0] = f2tf32(Ab[(rb)     * AS_STRIDE + k0 + qcol]);
                af[s][1] = f2tf32(Ab[(rb + 8) * AS_STRIDE + k0 + qcol]);
                af[s][2] = f2tf32(Ab[(rb)     * AS_STRIDE + k0 + qcol + 4]);
                af[s][3] = f2tf32(Ab[(rb + 8) * AS_STRIDE + k0 + qcol + 4]);
            }
            #pragma unroll
            for (int t = 0; t < 8; t++) {
                int n = 64 * wc + 8 * t + qrow;
                uint32_t b0 = __float_as_uint(Ws[(K0 + qcol)     * WS_STRIDE + n]);
                uint32_t b1 = __float_as_uint(Ws[(K0 + qcol + 4) * WS_STRIDE + n]);
                mma_tf32(acc[0][t], af[0], b0, b1);
                mma_tf32(acc[1][t], af[1], b0, b1);
            }
        }
        __syncthreads();
    }

    #pragma unroll
    for (int s = 0; s < 2; s++) {
        int rbase = row0 + 32 * wr + 16 * s + qrow;
        #pragma unroll
        for (int t = 0; t < 8; t++) {
            int col = 64 * wc + 8 * t + 2 * qcol;
            if (rbase < nrows)
                __stcs((float2*)(C + (size_t)rbase * FD + col),
                       make_float2(acc[s][t][0], acc[s][t][1]));
            if (rbase + 8 < nrows)
                __stcs((float2*)(C + (size_t)(rbase + 8) * FD + col),
                       make_float2(acc[s][t][2], acc[s][t][3]));
        }
    }
}

// ---------------- GCN aggregation: warp/node, streamed (src,w) edges -----------
__global__ void k_agg(const float* __restrict__ h, const float* __restrict__ bias,
                      float* __restrict__ out) {
    int gw = (blockIdx.x * blockDim.x + threadIdx.x) >> 5;
    if (gw >= NN) return;
    int lane = threadIdx.x & 31;
    int s = g_offs[gw], e = g_offs[gw + 1];

    float4 acc0 = make_float4(0.f, 0.f, 0.f, 0.f);
    float4 acc1 = make_float4(0.f, 0.f, 0.f, 0.f);

    int j = s;
    for (; j + 8 <= e; j += 8) {
        float2 ed[8];
        #pragma unroll
        for (int u = 0; u < 8; u++) ed[u] = __ldcs(&g_edge[j + u]);
        float4 v[8];
        #pragma unroll
        for (int u = 0; u < 8; u++)
            v[u] = ((const float4*)(h + (size_t)__float_as_int(ed[u].x) * FD))[lane];
        #pragma unroll
        for (int u = 0; u < 8; u += 2) {
            acc0.x = fmaf(ed[u].y, v[u].x, acc0.x); acc0.y = fmaf(ed[u].y, v[u].y, acc0.y);
            acc0.z = fmaf(ed[u].y, v[u].z, acc0.z); acc0.w = fmaf(ed[u].y, v[u].w, acc0.w);
            acc1.x = fmaf(ed[u+1].y, v[u+1].x, acc1.x); acc1.y = fmaf(ed[u+1].y, v[u+1].y, acc1.y);
            acc1.z = fmaf(ed[u+1].y, v[u+1].z, acc1.z); acc1.w = fmaf(ed[u+1].y, v[u+1].w, acc1.w);
        }
    }
    for (; j < e; j++) {
        float2 ej = __ldcs(&g_edge[j]);
        float4 v = ((const float4*)(h + (size_t)__float_as_int(ej.x) * FD))[lane];
        acc0.x = fmaf(ej.y, v.x, acc0.x); acc0.y = fmaf(ej.y, v.y, acc0.y);
        acc0.z = fmaf(ej.y, v.z, acc0.z); acc0.w = fmaf(ej.y, v.w, acc0.w);
    }
    {   // self loop
        float di = g_dinv[gw];
        float w = di * di;
        float4 v = ((const float4*)(h + (size_t)gw * FD))[lane];
        acc0.x = fmaf(w, v.x, acc0.x); acc0.y = fmaf(w, v.y, acc0.y);
        acc0.z = fmaf(w, v.z, acc0.z); acc0.w = fmaf(w, v.w, acc0.w);
    }
    float4 b4 = ((const float4*)bias)[lane];
    float4 r;
    r.x = fmaxf(acc0.x + acc1.x + b4.x, 0.f);
    r.y = fmaxf(acc0.y + acc1.y + b4.y, 0.f);
    r.z = fmaxf(acc0.z + acc1.z + b4.z, 0.f);
    r.w = fmaxf(acc0.w + acc1.w + b4.w, 0.f);
    __stcs((float4*)(out + (size_t)gw * FD) + lane, r);
}

// ---------------- per-graph mean pool (binary-search boundaries) ---------------
__global__ void k_pool(const float* __restrict__ h, const int* __restrict__ bat) {
    int g = blockIdx.x;
    __shared__ int se[2];
    if (threadIdx.x < 2) {
        int target = g + threadIdx.x;
        int lo = 0, hi = NN;
        while (lo < hi) { int m = (lo + hi) >> 1; if (bat[m] < target) lo = m + 1; else hi = m; }
        se[threadIdx.x] = lo;
    }
    __syncthreads();
    int s = se[0], e = se[1];
    int c = blockIdx.y * 32 + threadIdx.x;   // gridDim.y = 4
    float acc0 = 0.f, acc1 = 0.f, acc2 = 0.f, acc3 = 0.f;
    int i = s;
    for (; i + 4 <= e; i += 4) {
        acc0 += h[(size_t)(i + 0) * FD + c];
        acc1 += h[(size_t)(i + 1) * FD + c];
        acc2 += h[(size_t)(i + 2) * FD + c];
        acc3 += h[(size_t)(i + 3) * FD + c];
    }
    for (; i < e; i++) acc0 += h[(size_t)i * FD + c];
    float cnt = (float)((e - s) > 1 ? (e - s) : 1);
    g_pooled[g * FD + c] = (acc0 + acc1 + acc2 + acc3) / cnt;
}

// ---------------- final FC -------------------------------------------------------
__global__ void k_fc(const float* __restrict__ fcW, const float* __restrict__ fcb,
                     float* __restrict__ out) {
    int g = blockIdx.x;
    int c = threadIdx.x;
    float acc = fcb[c];
    #pragma unroll 4
    for (int k = 0; k < FD; k++)
        acc = fmaf(g_pooled[g * FD + k], fcW[k * NC + c], acc);
    out[g * NC + c] = acc;
}

// ---------------- launch ----------------------------------------------------------
extern "C" void kernel_launch(void* const* d_in, const int* in_sizes, int n_in,
                              void* d_out, int out_size) {
    const float* x    = (const float*)d_in[0];
    const int*   ei   = (const int*)d_in[1];
    const int*   bat  = (const int*)d_in[2];
    const float* W1   = (const float*)d_in[3];
    const float* b1   = (const float*)d_in[4];
    const float* W2   = (const float*)d_in[5];
    const float* b2   = (const float*)d_in[6];
    const float* fcW  = (const float*)d_in[7];
    const float* fcb  = (const float*)d_in[8];
    float* out = (float*)d_out;

    int ne = in_sizes[1] / 2;
    const int* src = ei;
    const int* dst = ei + ne;

    float *bufA, *bufB;
    cudaGetSymbolAddress((void**)&bufA, g_bufA);
    cudaGetSymbolAddress((void**)&bufB, g_bufB);

    cudaFuncSetAttribute(k_gemm_tf32, cudaFuncAttributeMaxDynamicSharedMemorySize, GEMM_SMEM);

    int tb = 256;
    int gbN   = (NN + tb - 1) / tb;
    int gbE   = (ne + tb - 1) / tb;
    int gbAgg = (NN * 32 + tb - 1) / tb;
    int gbGemm = (NN + 127) / 128;

    // ordered so launch index 3 (profiled slot) is the layer-1 GEMM
    k_init<<<gbN, tb>>>();                                          // 0
    k_deg<<<gbE, tb>>>(dst, ne);                                    // 1
    k_blocksum<<<NBLK, tb>>>();                                     // 2
    k_gemm_tf32<<<gbGemm, tb, GEMM_SMEM>>>(x, W1, bufA, NN);        // 3 <- profiled
    k_scanpartials<<<1, 512>>>();                                   // 4
    k_offsets<<<NBLK, tb>>>();                                      // 5
    k_scatter<<<gbE, tb>>>(src, dst, ne);                           // 6
    k_agg<<<gbAgg, tb>>>(bufA, b1, bufB);                           // 7
    k_gemm_tf32<<<gbGemm, tb, GEMM_SMEM>>>(bufB, W2, bufA, NN);     // 8
    k_agg<<<gbAgg, tb>>>(bufA, b2, bufB);                           // 9
    k_pool<<<dim3(NG, 4), 32>>>(bufB, bat);                         // 10
    k_fc<<<NG, NC>>>(fcW, fcb, out);                                // 11
}